// round 4
// baseline (speedup 1.0000x reference)
#include <cuda_runtime.h>

#define N_NODES 100000
#define E_EDGES 1600000
#define ET (E_EDGES + N_NODES)   // edges + self loops
#define NEG 0.2f
#define EPSV 1e-16f

// Scratch (no allocs allowed): per-(node, head-pair) accumulators.
// g_s1[n*4+g] = (num_{2g}, den_{2g}, num_{2g+1}, den_{2g+1})
__device__ float4 g_s1[N_NODES * 4];
__device__ float2 g_s2[N_NODES];      // layer2 (num, den)
__device__ float  g_h2[N_NODES];      // layer2 node features (scalar)
__device__ float  g_S1[8];            // sum_c W1[h,c]*att_src1[h,c]
__device__ float  g_D1[8];
__device__ float  g_sc2[3];           // att_src2, att_dst2, b2

// ---------------- tiny precompute: per-head logit coefficients ----------
__global__ void k_pre(const float* __restrict__ W1,
                      const float* __restrict__ as1,
                      const float* __restrict__ ad1,
                      const float* __restrict__ as2,
                      const float* __restrict__ ad2,
                      const float* __restrict__ b2) {
    int h = threadIdx.x;
    if (h < 8) {
        float s = 0.f, d = 0.f;
        #pragma unroll
        for (int c = 0; c < 16; c++) {
            float w = W1[h * 16 + c];
            s += w * as1[h * 16 + c];
            d += w * ad1[h * 16 + c];
        }
        g_S1[h] = s;
        g_D1[h] = d;
    }
    if (h == 0) { g_sc2[0] = as2[0]; g_sc2[1] = ad2[0]; g_sc2[2] = b2[0]; }
}

// ---------------- zero layer-1 accumulators ----------------------------
__global__ void k_zero() {
    int i = blockIdx.x * blockDim.x + threadIdx.x;
    if (i < N_NODES * 4) g_s1[i] = make_float4(0.f, 0.f, 0.f, 0.f);
}

// ---------------- layer-1 edge pass (softmax num/den accumulation) -----
__global__ void __launch_bounds__(256)
k_e1(const int* __restrict__ src, const int* __restrict__ dst,
     const float* __restrict__ x) {
    int i = blockIdx.x * blockDim.x + threadIdx.x;
    if (i >= ET) return;
    int s, d;
    if (i < E_EDGES) { s = src[i]; d = dst[i]; }
    else             { s = d = i - E_EDGES; }   // self-loop
    float xs = __ldg(x + s);
    float xd = __ldg(x + d);
    float4* base = &g_s1[(size_t)d * 4];
    #pragma unroll
    for (int g = 0; g < 4; g++) {
        float e0 = xs * g_S1[2 * g]     + xd * g_D1[2 * g];
        float e1 = xs * g_S1[2 * g + 1] + xd * g_D1[2 * g + 1];
        e0 = e0 > 0.f ? e0 : NEG * e0;           // leaky_relu
        e1 = e1 > 0.f ? e1 : NEG * e1;
        float x0 = __expf(e0), x1 = __expf(e1);  // no max-shift needed (bounded)
        atomicAdd(base + g, make_float4(x0 * xs, x0, x1 * xs, x1));
    }
}

// ---------------- layer-1 epilogue + layer-2 projection (per node) -----
__global__ void __launch_bounds__(128)
k_n1(const float* __restrict__ W1, const float* __restrict__ b1,
     const float* __restrict__ W2) {
    __shared__ float sW1[128], sb1[128], sW2[128];
    int t = threadIdx.x;
    sW1[t] = W1[t]; sb1[t] = b1[t]; sW2[t] = W2[t];
    __syncthreads();
    int n = blockIdx.x * 128 + t;
    if (n >= N_NODES) return;
    float acc = 0.f;
    #pragma unroll
    for (int g = 0; g < 4; g++) {
        float4 v = g_s1[(size_t)n * 4 + g];
        float t0 = v.x / (v.y + EPSV);           // attention-weighted mean of x
        float t1 = v.z / (v.w + EPSV);
        #pragma unroll
        for (int c = 0; c < 16; c++) {
            int k0 = (2 * g) * 16 + c, k1 = (2 * g + 1) * 16 + c;
            float u0 = t0 * sW1[k0] + sb1[k0];
            float u1 = t1 * sW1[k1] + sb1[k1];
            u0 = u0 > 0.f ? u0 : expm1f(u0);     // elu
            u1 = u1 > 0.f ? u1 : expm1f(u1);
            acc += u0 * sW2[k0] + u1 * sW2[k1];
        }
    }
    g_h2[n] = acc;
    g_s2[n] = make_float2(0.f, 0.f);             // zero layer-2 accumulators
}

// ---------------- layer-2 edge pass ------------------------------------
__global__ void __launch_bounds__(256)
k_e2(const int* __restrict__ src, const int* __restrict__ dst) {
    int i = blockIdx.x * blockDim.x + threadIdx.x;
    if (i >= ET) return;
    int s, d;
    if (i < E_EDGES) { s = src[i]; d = dst[i]; }
    else             { s = d = i - E_EDGES; }
    const float* h2 = (const float*)g_h2;
    float hs = __ldg(h2 + s);
    float hd = __ldg(h2 + d);
    float e = hs * g_sc2[0] + hd * g_sc2[1];
    e = e > 0.f ? e : NEG * e;
    float ex = __expf(e);
    atomicAdd(&g_s2[d], make_float2(ex * hs, ex));
}

// ---------------- output -----------------------------------------------
__global__ void k_n2(float* __restrict__ out) {
    int n = blockIdx.x * blockDim.x + threadIdx.x;
    if (n >= N_NODES) return;
    float2 v = g_s2[n];
    out[n] = v.x / (v.y + EPSV) + g_sc2[2];
}

extern "C" void kernel_launch(void* const* d_in, const int* in_sizes, int n_in,
                              void* d_out, int out_size) {
    const float* x   = (const float*)d_in[0];
    const int*   ei  = (const int*)d_in[1];   // int64 in reference -> int32 in harness
    const float* W1  = (const float*)d_in[2];
    const float* as1 = (const float*)d_in[3];
    const float* ad1 = (const float*)d_in[4];
    const float* b1  = (const float*)d_in[5];
    const float* W2  = (const float*)d_in[6];
    const float* as2 = (const float*)d_in[7];
    const float* ad2 = (const float*)d_in[8];
    const float* b2  = (const float*)d_in[9];
    float* out = (float*)d_out;

    const int* src = ei;
    const int* dst = ei + E_EDGES;

    k_pre<<<1, 32>>>(W1, as1, ad1, as2, ad2, b2);
    k_zero<<<(N_NODES * 4 + 255) / 256, 256>>>();
    k_e1<<<(ET + 255) / 256, 256>>>(src, dst, x);
    k_n1<<<(N_NODES + 127) / 128, 128>>>(W1, b1, W2);
    k_e2<<<(ET + 255) / 256, 256>>>(src, dst);
    k_n2<<<(N_NODES + 255) / 256, 256>>>(out);
}

// round 5
// speedup vs baseline: 1.6940x; 1.6940x over previous
#include <cuda_runtime.h>

#define N_NODES 100000
#define E_EDGES 1600000
#define ET (E_EDGES + N_NODES)   // edges + self loops
#define NEG 0.2f
#define EPSV 1e-16f

// Scratch (no allocs allowed): per-(node, head-pair) accumulators.
// g_s1[n*4+g] = (num_{2g}, den_{2g}, num_{2g+1}, den_{2g+1})
__device__ float4 g_s1[N_NODES * 4];
__device__ float2 g_s2[N_NODES];      // layer2 (num, den)
__device__ float  g_h2[N_NODES];      // layer2 node features (scalar)
__device__ float  g_S1[8];            // sum_c W1[h,c]*att_src1[h,c]
__device__ float  g_D1[8];
__device__ float  g_sc2[3];           // att_src2, att_dst2, b2

// ---------------- zero accumulators + per-head logit coefficients -------
__global__ void k_zero(const float* __restrict__ W1,
                       const float* __restrict__ as1,
                       const float* __restrict__ ad1,
                       const float* __restrict__ as2,
                       const float* __restrict__ ad2,
                       const float* __restrict__ b2) {
    int i = blockIdx.x * blockDim.x + threadIdx.x;
    if (i < N_NODES * 4) g_s1[i] = make_float4(0.f, 0.f, 0.f, 0.f);
    if (blockIdx.x == 0) {
        int h = threadIdx.x;
        if (h < 8) {
            float s = 0.f, d = 0.f;
            #pragma unroll
            for (int c = 0; c < 16; c++) {
                float w = W1[h * 16 + c];
                s += w * as1[h * 16 + c];
                d += w * ad1[h * 16 + c];
            }
            g_S1[h] = s;
            g_D1[h] = d;
        }
        if (h == 8) { g_sc2[0] = as2[0]; g_sc2[1] = ad2[0]; g_sc2[2] = b2[0]; }
    }
}

// ---------------- layer-1 edge pass (softmax num/den accumulation) -----
__global__ void __launch_bounds__(256)
k_e1(const int* __restrict__ src, const int* __restrict__ dst,
     const float* __restrict__ x) {
    int i = blockIdx.x * blockDim.x + threadIdx.x;
    if (i >= ET) return;
    int s, d;
    if (i < E_EDGES) { s = src[i]; d = dst[i]; }
    else             { s = d = i - E_EDGES; }   // self-loop
    float xs = __ldg(x + s);
    float xd = __ldg(x + d);
    float4* base = &g_s1[(size_t)d * 4];
    #pragma unroll
    for (int g = 0; g < 4; g++) {
        float e0 = xs * g_S1[2 * g]     + xd * g_D1[2 * g];
        float e1 = xs * g_S1[2 * g + 1] + xd * g_D1[2 * g + 1];
        e0 = e0 > 0.f ? e0 : NEG * e0;           // leaky_relu
        e1 = e1 > 0.f ? e1 : NEG * e1;
        float x0 = __expf(e0), x1 = __expf(e1);  // no max-shift needed (bounded)
        atomicAdd(base + g, make_float4(x0 * xs, x0, x1 * xs, x1));
    }
}

// ---------------- layer-1 epilogue + layer-2 projection (per node) -----
__global__ void __launch_bounds__(128)
k_n1(const float* __restrict__ W1, const float* __restrict__ b1,
     const float* __restrict__ W2) {
    __shared__ float sW1[128], sb1[128], sW2[128];
    int t = threadIdx.x;
    sW1[t] = W1[t]; sb1[t] = b1[t]; sW2[t] = W2[t];
    __syncthreads();
    int n = blockIdx.x * 128 + t;
    if (n >= N_NODES) return;
    float acc = 0.f;
    #pragma unroll
    for (int g = 0; g < 4; g++) {
        float4 v = g_s1[(size_t)n * 4 + g];
        float t0 = __fdividef(v.x, v.y + EPSV);  // attention-weighted mean of x
        float t1 = __fdividef(v.z, v.w + EPSV);
        #pragma unroll
        for (int c = 0; c < 16; c++) {
            int k0 = (2 * g) * 16 + c, k1 = (2 * g + 1) * 16 + c;
            float u0 = t0 * sW1[k0] + sb1[k0];
            float u1 = t1 * sW1[k1] + sb1[k1];
            // elu: u<0 -> exp(u)-1 (u bounded, __expf error ~1e-8 abs here)
            u0 = u0 > 0.f ? u0 : __expf(u0) - 1.f;
            u1 = u1 > 0.f ? u1 : __expf(u1) - 1.f;
            acc += u0 * sW2[k0] + u1 * sW2[k1];
        }
    }
    g_h2[n] = acc;
    g_s2[n] = make_float2(0.f, 0.f);             // zero layer-2 accumulators
}

// ---------------- layer-2 edge pass ------------------------------------
__global__ void __launch_bounds__(256)
k_e2(const int* __restrict__ src, const int* __restrict__ dst) {
    int i = blockIdx.x * blockDim.x + threadIdx.x;
    if (i >= ET) return;
    int s, d;
    if (i < E_EDGES) { s = src[i]; d = dst[i]; }
    else             { s = d = i - E_EDGES; }
    const float* h2 = (const float*)g_h2;
    float hs = __ldg(h2 + s);
    float hd = __ldg(h2 + d);
    float e = hs * g_sc2[0] + hd * g_sc2[1];
    e = e > 0.f ? e : NEG * e;
    float ex = __expf(e);
    atomicAdd(&g_s2[d], make_float2(ex * hs, ex));
}

// ---------------- output -----------------------------------------------
__global__ void k_n2(float* __restrict__ out) {
    int n = blockIdx.x * blockDim.x + threadIdx.x;
    if (n >= N_NODES) return;
    float2 v = g_s2[n];
    out[n] = __fdividef(v.x, v.y + EPSV) + g_sc2[2];
}

extern "C" void kernel_launch(void* const* d_in, const int* in_sizes, int n_in,
                              void* d_out, int out_size) {
    const float* x   = (const float*)d_in[0];
    const int*   ei  = (const int*)d_in[1];   // int64 in reference -> int32 in harness
    const float* W1  = (const float*)d_in[2];
    const float* as1 = (const float*)d_in[3];
    const float* ad1 = (const float*)d_in[4];
    const float* b1  = (const float*)d_in[5];
    const float* W2  = (const float*)d_in[6];
    const float* as2 = (const float*)d_in[7];
    const float* ad2 = (const float*)d_in[8];
    const float* b2  = (const float*)d_in[9];
    float* out = (float*)d_out;

    const int* src = ei;
    const int* dst = ei + E_EDGES;

    k_zero<<<(N_NODES * 4 + 255) / 256, 256>>>(W1, as1, ad1, as2, ad2, b2);
    k_e1<<<(ET + 255) / 256, 256>>>(src, dst, x);
    k_n1<<<(N_NODES + 127) / 128, 128>>>(W1, b1, W2);
    k_e2<<<(ET + 255) / 256, 256>>>(src, dst);
    k_n2<<<(N_NODES + 255) / 256, 256>>>(out);
}